// round 7
// baseline (speedup 1.0000x reference)
#include <cuda_runtime.h>
#include <limits.h>

// CTC loss forward, warp-specialized (1 compute + 3 loader warps per CTA).
// Block-rebased extended-range arithmetic (proven in R6):
//   alpha[s] = u[s] * 2^Eb[s], Eb rebased every RSTEPS=4 steps to
//   E'[s] = max(Et[s-8..s]); per-step scales sb, sc become constants.
// Producer/consumer handoff via per-row flags: st.release.cta (producer
// lane 0 after __syncwarp) / ld.acquire.cta (consumer). No MEMBAR.ALL.CTA
// anywhere in the steady state.

#define NST    5
#define RSTEPS 4
#define RD     32          // ring rows (power of 2)
#define BPMARG 4           // loader may lead cons by < RD-BPMARG rows
#define DEPTH  4           // loader LDG pipeline depth
#define SENT   (-(1 << 28))

__device__ float    g_loss[1024];
__device__ unsigned g_cnt = 0;

__device__ __forceinline__ void st_release_cta(int* p, int v) {
    asm volatile("st.release.cta.b32 [%0], %1;" :: "l"(p), "r"(v) : "memory");
}
__device__ __forceinline__ int ld_acquire_cta(const int* p) {
    int v;
    asm volatile("ld.acquire.cta.b32 %0, [%1];" : "=r"(v) : "l"(p) : "memory");
    return v;
}

__global__ void __launch_bounds__(128, 1)
ctc_ws3_kernel(const float* __restrict__ logp,
               const int*   __restrict__ targets,
               const int*   __restrict__ in_len,
               const int*   __restrict__ tgt_len,
               float*       __restrict__ out,
               int T, int B, int C, int S)
{
    const int b    = blockIdx.x;
    const int tid  = threadIdx.x;
    const int w    = tid >> 5;
    const int lane = tid & 31;
    const int L    = 2 * S + 1;
    const int* tgt = targets + (size_t)b * S;

    __shared__ float        ring[RD][NST * 32];   // [row][j*32+lane]
    __shared__ int          flg[RD];              // row-ready flags (t value)
    __shared__ float        scratch[3][256];
    __shared__ volatile int consV;
    __shared__ float        fv[NST * 32];
    __shared__ int          fe[NST * 32];
    __shared__ float        red[4];
    __shared__ int          s_last;

    const size_t BC   = (size_t)B * C;
    const float* base = logp + (size_t)b * C;

    int len = in_len[b];
    if (len > T) len = T;
    if (len < 1) len = 1;
    const int lenm1 = len - 1;

    if (tid == 0) consV = 0;
    if (tid < RD) flg[tid] = 0;
    __syncthreads();

    if (w == 0) {
        // ================= compute warp =================
        int skm[NST];
#pragma unroll
        for (int j = 0; j < NST; ++j) {
            int s = lane * NST + j;
            int sk = 0;
            if (s < L && s >= 3 && (s & 1)) {
                int lab = tgt[s >> 1];
                int lm2 = tgt[(s - 2) >> 1];
                if (lab != 0 && lab != lm2) sk = 1;
            }
            skm[j] = sk;
        }

        float u[NST];  int Eb[NST];
#pragma unroll
        for (int j = 0; j < NST; ++j) { u[j] = 0.0f; Eb[j] = SENT; }
        if (lane == 0) {
            float y0 = __ldg(base) * 1.4426950408889634f;
            float f0 = floorf(y0); Eb[0] = (int)f0; u[0] = exp2f(y0 - f0);
            if (L > 1) {
                int lab1 = tgt[0];
                float y1 = __ldg(base + lab1) * 1.4426950408889634f;
                float f1 = floorf(y1); Eb[1] = (int)f1; u[1] = exp2f(y1 - f1);
            }
        }

        for (int t0 = 1; t0 < len; t0 += RSTEPS) {
            int tend = t0 + RSTEPS; if (tend > len) tend = len;

            // ---- wait for this block's rows (acquire), then preload p ----
#pragma unroll
            for (int k = 0; k < RSTEPS; ++k) {
                int t = t0 + k;
                if (t < len) {
                    int* fp = &flg[t & (RD - 1)];
                    while (ld_acquire_cta(fp) != t) { }
                }
            }
            float P[RSTEPS][NST];
#pragma unroll
            for (int k = 0; k < RSTEPS; ++k) {
                int t = t0 + k; if (t > lenm1) t = lenm1;
                const float* rp = &ring[t & (RD - 1)][0];
#pragma unroll
                for (int j = 0; j < NST; ++j) P[k][j] = rp[j * 32 + lane];
            }

            // ---------- REBASE (overlaps the p LDS latency) ----------
            int Et[NST]; int mb[NST];
#pragma unroll
            for (int j = 0; j < NST; ++j) {
                int bits = __float_as_int(u[j]);
                int ex   = (bits >> 23) & 0xff;
                Et[j] = (ex == 0) ? SENT : (Eb[j] + ex - 127);
                mb[j] = bits & 0x007fffff;
            }
            int P0 = Et[0];
            int P1 = max(P0, Et[1]);
            int P2 = max(P1, Et[2]);
            int P3 = max(P2, Et[3]);
            int P4 = max(P3, Et[4]);
            int S4 = Et[4];
            int S3 = max(Et[3], S4);
            int S2 = max(Et[2], S3);
            int S1 = max(Et[1], S2);
            int M_l1  = __shfl_up_sync(0xffffffffu, P4, 1); if (lane < 1) M_l1  = SENT;
            int S1_l1 = __shfl_up_sync(0xffffffffu, S1, 1); if (lane < 1) S1_l1 = SENT;
            int S2_l2 = __shfl_up_sync(0xffffffffu, S2, 2); if (lane < 2) S2_l2 = SENT;
            int S3_l2 = __shfl_up_sync(0xffffffffu, S3, 2); if (lane < 2) S3_l2 = SENT;
            int S4_l2 = __shfl_up_sync(0xffffffffu, S4, 2); if (lane < 2) S4_l2 = SENT;
            int E0 = max(max(S2_l2, M_l1), P0);
            int E1 = max(max(S3_l2, M_l1), P1);
            int E2 = max(max(S4_l2, M_l1), P2);
            int E3 = max(M_l1, P3);
            int E4 = max(S1_l1, P4);
            int En[NST] = {E0, E1, E2, E3, E4};
#pragma unroll
            for (int j = 0; j < NST; ++j) {
                int d = Et[j] - En[j];                 // <= 0
                u[j] = (d < -126 || Et[j] <= SENT) ? 0.0f
                     : __int_as_float(mb[j] | ((d + 127) << 23));
            }
            int E4_l1 = __shfl_up_sync(0xffffffffu, E4, 1); if (lane < 1) E4_l1 = SENT;
            int E3_l1 = __shfl_up_sync(0xffffffffu, E3, 1); if (lane < 1) E3_l1 = SENT;
            int Em1[NST] = {E4_l1, E0, E1, E2, E3};
            int Em2[NST] = {E3_l1, E4_l1, E0, E1, E2};
            float sb[NST], sc[NST];
#pragma unroll
            for (int j = 0; j < NST; ++j) {
                int db = min(Em1[j] - En[j], 126);
                sb[j] = (db < -126 || Em1[j] <= SENT) ? 0.0f
                      : __int_as_float((db + 127) << 23);
                int dc = min(Em2[j] - En[j], 126);
                float scv = (dc < -126 || Em2[j] <= SENT) ? 0.0f
                          : __int_as_float((dc + 127) << 23);
                sc[j] = skm[j] ? scv : 0.0f;
                Eb[j] = En[j];
            }

            // ---------- 4 cheap steps (registers only) ----------
#pragma unroll
            for (int k = 0; k < RSTEPS; ++k) {
                int t = t0 + k;
                if (t < len) {
                    float vm1 = __shfl_up_sync(0xffffffffu, u[4], 1);
                    float vm2 = __shfl_up_sync(0xffffffffu, u[3], 1);
                    if (lane == 0) { vm1 = 0.0f; vm2 = 0.0f; }
                    float n0 = fmaf(vm2,  sc[0], fmaf(vm1,  sb[0], u[0])) * P[k][0];
                    float n1 = fmaf(vm1,  sc[1], fmaf(u[0], sb[1], u[1])) * P[k][1];
                    float n2 = fmaf(u[0], sc[2], fmaf(u[1], sb[2], u[2])) * P[k][2];
                    float n3 = fmaf(u[1], sc[3], fmaf(u[2], sb[3], u[3])) * P[k][3];
                    float n4 = fmaf(u[2], sc[4], fmaf(u[3], sb[4], u[4])) * P[k][4];
                    u[0] = n0; u[1] = n1; u[2] = n2; u[3] = n3; u[4] = n4;
                }
            }
            if (lane == 0) consV = tend - 1;      // throttle info for loaders
        }

        // final extraction
#pragma unroll
        for (int j = 0; j < NST; ++j) {
            int bits = __float_as_int(u[j]);
            int ex   = (bits >> 23) & 0xff;
            fe[lane * NST + j] = (ex == 0) ? SENT : (Eb[j] + ex - 127);
            fv[lane * NST + j] = __int_as_float((bits & 0x007fffff) | 0x3f800000);
        }
    } else {
        // ================= loader warp i (0..2) =================
        const int i  = w - 1;
        const int c0 = lane * 8;
        const float* src = base + c0;

        int lab2[NST];
#pragma unroll
        for (int j = 0; j < NST; ++j) {
            int s = lane * NST + j;
            int lab = 0;
            if (s < L && (s & 1)) lab = tgt[s >> 1];
            lab2[j] = lab;
        }

        float4 Aa[DEPTH], Ab[DEPTH];
        int tf = 1 + i;
#pragma unroll
        for (int k = 0; k < DEPTH; ++k) {
            int tt = tf; if (tt > lenm1) tt = lenm1; if (tt < 1) tt = 1;
            const float* r = src + (size_t)tt * BC;
            Aa[k] = *(const float4*)r;
            Ab[k] = *(const float4*)(r + 4);
            tf += 3;
        }
        int kk = 0, consv = 0;
        for (int t = 1 + i; t <= lenm1; t += 3) {
            while (t - consv >= RD - BPMARG) consv = consV;   // backpressure
            float4 a = Aa[kk], q = Ab[kk];
            float* scr = &scratch[i][c0];
            ((float4*)scr)[0] = make_float4(__expf(a.x), __expf(a.y),
                                            __expf(a.z), __expf(a.w));
            ((float4*)scr)[1] = make_float4(__expf(q.x), __expf(q.y),
                                            __expf(q.z), __expf(q.w));
            __syncwarp();
            float* dst = &ring[t & (RD - 1)][0];
#pragma unroll
            for (int j = 0; j < NST; ++j)
                dst[j * 32 + lane] = scratch[i][lab2[j]];
            __syncwarp();                     // all lanes' STS before flag
            if (lane == 0) st_release_cta(&flg[t & (RD - 1)], t);
            if (tf <= lenm1) {                // refill stage kk
                const float* r = src + (size_t)tf * BC;
                Aa[kk] = *(const float4*)r;
                Ab[kk] = *(const float4*)(r + 4);
            }
            tf += 3;
            kk = (kk == DEPTH - 1) ? 0 : kk + 1;
        }
    }
    __syncthreads();

    // ---- per-batch loss ----
    if (tid == 0) {
        int tl = tgt_len[b];
        int hi = 2 * tl; if (hi > L - 1) hi = L - 1;
        float loss = 0.0f;
        if (tl > 0) {
            int   ea = fe[hi];                 float va = fv[hi];
            int   eb = (hi >= 1) ? fe[hi - 1] : SENT;
            float vb = (hi >= 1) ? fv[hi - 1] : 1.0f;
            int mx = max(ea, eb);
            if (mx > SENT / 2) {
                float sa  = (ea - mx < -126) ? 0.0f
                          : va * __int_as_float((ea - mx + 127) << 23);
                float sbv = (eb - mx < -126 || eb <= SENT) ? 0.0f
                          : vb * __int_as_float((eb - mx + 127) << 23);
                double ll = ((double)mx + (double)log2f(sa + sbv)) * 0.69314718055994530942;
                loss = (float)(-ll / (double)tl);
            }
        }
        g_loss[b] = loss;
        __threadfence();
        unsigned old = atomicAdd(&g_cnt, 1);
        s_last = (old == (unsigned)(gridDim.x - 1)) ? 1 : 0;
    }
    __syncthreads();

    // ---- last CTA: fused mean reduction ----
    if (s_last) {
        __threadfence();
        float acc = 0.0f;
        for (int i2 = tid; i2 < B; i2 += 128) acc += g_loss[i2];
#pragma unroll
        for (int o = 16; o > 0; o >>= 1)
            acc += __shfl_xor_sync(0xffffffffu, acc, o);
        if (lane == 0) red[w] = acc;
        __syncthreads();
        if (tid == 0) {
            out[0] = (red[0] + red[1] + red[2] + red[3]) / (float)B;
            g_cnt = 0;   // reset for next graph replay
        }
    }
}

extern "C" void kernel_launch(void* const* d_in, const int* in_sizes, int n_in,
                              void* d_out, int out_size)
{
    const float* logp    = (const float*)d_in[0];
    const int*   targets = (const int*)d_in[1];
    const int*   in_len  = (const int*)d_in[2];
    const int*   tgt_len = (const int*)d_in[3];

    int B = in_sizes[2];                                   // 128
    int S = in_sizes[1] / B;                               // 64
    int C = 256;
    int T = (int)((size_t)in_sizes[0] / ((size_t)B * C));  // 1024

    ctc_ws3_kernel<<<B, 128>>>(logp, targets, in_len, tgt_len,
                               (float*)d_out, T, B, C, S);
}

// round 8
// speedup vs baseline: 2.4778x; 2.4778x over previous
#include <cuda_runtime.h>

// CTC loss forward, bisected (forward alpha + backward gamma meet at tm)
// with warp-specialized loaders. Per CTA (one batch element), 256 threads:
//   w0: forward compute   (alpha, states ascending, shfl_up)
//   w1: backward compute  (gamma, states descending, shfl_down)
//   w2-4: forward loaders (rows 1..tm)        w5-7: backward loaders (rows len-1..tm+1)
// Extended-range alpha[s] = u[s]*2^Eb[s], block-rebased every RSTEPS=4 steps.
// Loader prefetch buffers are STATICALLY indexed (fully unrolled stage loop)
// so they live in registers and LDG latency is covered by DEPTH iterations.

#define NST    5
#define RSTEPS 4
#define RD     16          // ring rows per direction (power of 2)
#define LEAD   12          // loader may lead consumed row by < LEAD
#define DEPTH  6           // loader LDG pipeline depth (static stages)
#define SENT   (-(1 << 28))

__device__ float    g_loss[1024];
__device__ unsigned g_cnt = 0;

__device__ __forceinline__ void st_release_cta(int* p, int v) {
    asm volatile("st.release.cta.b32 [%0], %1;" :: "l"(p), "r"(v) : "memory");
}
__device__ __forceinline__ int ld_acquire_cta(const int* p) {
    int v;
    asm volatile("ld.acquire.cta.b32 %0, [%1];" : "=r"(v) : "l"(p) : "memory");
    return v;
}
__device__ __forceinline__ int iclamp(int x, int lo, int hi) {
    return min(max(x, lo), hi);
}
__device__ __forceinline__ float mkscale(int d) {   // 2^d for d in [-126,126]
    return __int_as_float((d + 127) << 23);
}

// Loader warp: stream rows [t_begin, t_begin+stride, ...] (cnt rows),
// exp() whole row, gather per-state probs into ring, set flag.
__device__ __forceinline__ void loader_warp(
    const float* src, size_t BC,
    int t_begin, int cnt, int stride, int lo, int hi,
    float (*ring)[NST * 32], int* flg,
    volatile int* consP, int consSign,
    float* scratch, const int* lab2, int lane)
{
    float4 Aa[DEPTH], Ab[DEPTH];
    int tq = t_begin;
#pragma unroll
    for (int k = 0; k < DEPTH; ++k) {
        int tt = iclamp(tq, lo, hi);
        const float* r = src + (size_t)tt * BC;
        Aa[k] = *(const float4*)r;
        Ab[k] = *(const float4*)(r + 4);
        tq += stride;
    }
    int t = t_begin;
    int consv = *consP;
    const int c0 = lane * 8;
    while (cnt > 0) {
#pragma unroll
        for (int k = 0; k < DEPTH; ++k) {
            if (cnt > 0) {
                for (;;) {                       // backpressure
                    int lead = (consSign > 0) ? (t - consv) : (consv - t);
                    if (lead < LEAD) break;
                    __nanosleep(100);
                    consv = *consP;
                }
                float4 a = Aa[k], q = Ab[k];
                float* scr = scratch + c0;
                ((float4*)scr)[0] = make_float4(__expf(a.x), __expf(a.y),
                                                __expf(a.z), __expf(a.w));
                ((float4*)scr)[1] = make_float4(__expf(q.x), __expf(q.y),
                                                __expf(q.z), __expf(q.w));
                __syncwarp();
                float* dst = ring[t & (RD - 1)];
#pragma unroll
                for (int j = 0; j < NST; ++j)
                    dst[j * 32 + lane] = scratch[lab2[j]];
                __syncwarp();
                if (lane == 0) st_release_cta(&flg[t & (RD - 1)], t);
                int tt = iclamp(tq, lo, hi);     // refill stage k (static idx)
                const float* r = src + (size_t)tt * BC;
                Aa[k] = *(const float4*)r;
                Ab[k] = *(const float4*)(r + 4);
                tq += stride;
                t += stride;
                --cnt;
            }
        }
    }
}

__global__ void __launch_bounds__(256, 1)
ctc_bisect_kernel(const float* __restrict__ logp,
                  const int*   __restrict__ targets,
                  const int*   __restrict__ in_len,
                  const int*   __restrict__ tgt_len,
                  float*       __restrict__ out,
                  int T, int B, int C, int S)
{
    const int b    = blockIdx.x;
    const int tid  = threadIdx.x;
    const int w    = tid >> 5;
    const int lane = tid & 31;
    const int L    = 2 * S + 1;
    const int* tgt = targets + (size_t)b * S;

    __shared__ float        ringF[RD][NST * 32];
    __shared__ float        ringB[RD][NST * 32];
    __shared__ int          flgF[RD], flgB[RD];
    __shared__ float        scratchA[6][256];
    __shared__ volatile int consF, consB;
    __shared__ float        fvF[NST * 32]; __shared__ int feF[NST * 32];
    __shared__ float        fvB[NST * 32]; __shared__ int feB[NST * 32];
    __shared__ float        red[8];
    __shared__ int          s_last;

    const size_t BC   = (size_t)B * C;
    const float* base = logp + (size_t)b * C;

    int len = in_len[b];
    if (len > T) len = T;
    if (len < 1) len = 1;
    const int lenm1 = len - 1;
    const int tm    = lenm1 >> 1;        // forward runs t=1..tm
    const int tmp1  = tm + 1;            // backward runs t=len-1..tm+1
    const bool use_gamma = (lenm1 > tm);

    if (tid == 0) { consF = 0; consB = len; }
    if (tid < RD) { flgF[tid] = 0; flgB[tid] = 0; }
    __syncthreads();

    if (w == 0) {
        // ================= forward compute (alpha) =================
        int skm[NST];
#pragma unroll
        for (int j = 0; j < NST; ++j) {
            int s = lane * NST + j;
            int sk = 0;
            if (s < L && s >= 3 && (s & 1)) {
                int lab = tgt[s >> 1];
                int lm2 = tgt[(s - 2) >> 1];
                if (lab != 0 && lab != lm2) sk = 1;
            }
            skm[j] = sk;
        }
        float u[NST]; int Eb[NST];
#pragma unroll
        for (int j = 0; j < NST; ++j) { u[j] = 0.0f; Eb[j] = SENT; }
        if (lane == 0) {
            float y0 = __ldg(base) * 1.4426950408889634f;
            float f0 = floorf(y0); Eb[0] = (int)f0; u[0] = exp2f(y0 - f0);
            if (L > 1) {
                int lab1 = tgt[0];
                float y1 = __ldg(base + lab1) * 1.4426950408889634f;
                float f1 = floorf(y1); Eb[1] = (int)f1; u[1] = exp2f(y1 - f1);
            }
        }

        for (int t0 = 1; t0 <= tm; t0 += RSTEPS) {
            int tend = t0 + RSTEPS - 1; if (tend > tm) tend = tm;
            // wait flags then preload p
#pragma unroll
            for (int k = 0; k < RSTEPS; ++k) {
                int t = t0 + k;
                if (t <= tm) {
                    int* fp = &flgF[t & (RD - 1)];
                    while (ld_acquire_cta(fp) != t) { }
                }
            }
            float P[RSTEPS][NST];
#pragma unroll
            for (int k = 0; k < RSTEPS; ++k) {
                int t = t0 + k; if (t > tm) t = tm;
                const float* rp = &ringF[t & (RD - 1)][0];
#pragma unroll
                for (int j = 0; j < NST; ++j) P[k][j] = rp[j * 32 + lane];
            }
            // ---- rebase (window s-8..s) ----
            int Et[NST], mb[NST];
#pragma unroll
            for (int j = 0; j < NST; ++j) {
                int bits = __float_as_int(u[j]);
                int ex   = (bits >> 23) & 0xff;
                Et[j] = (ex == 0) ? SENT : (Eb[j] + ex - 127);
                mb[j] = bits & 0x007fffff;
            }
            int P0 = Et[0];
            int P1 = max(P0, Et[1]);
            int P2 = max(P1, Et[2]);
            int P3 = max(P2, Et[3]);
            int P4 = max(P3, Et[4]);
            int S4 = Et[4];
            int S3 = max(Et[3], S4);
            int S2 = max(Et[2], S3);
            int S1 = max(Et[1], S2);
            int M_l1  = __shfl_up_sync(0xffffffffu, P4, 1); if (lane < 1) M_l1  = SENT;
            int S1_l1 = __shfl_up_sync(0xffffffffu, S1, 1); if (lane < 1) S1_l1 = SENT;
            int S2_l2 = __shfl_up_sync(0xffffffffu, S2, 2); if (lane < 2) S2_l2 = SENT;
            int S3_l2 = __shfl_up_sync(0xffffffffu, S3, 2); if (lane < 2) S3_l2 = SENT;
            int S4_l2 = __shfl_up_sync(0xffffffffu, S4, 2); if (lane < 2) S4_l2 = SENT;
            int E0 = max(max(S2_l2, M_l1), P0);
            int E1 = max(max(S3_l2, M_l1), P1);
            int E2 = max(max(S4_l2, M_l1), P2);
            int E3 = max(M_l1, P3);
            int E4 = max(S1_l1, P4);
            int En[NST] = {E0, E1, E2, E3, E4};
#pragma unroll
            for (int j = 0; j < NST; ++j) {
                int d = Et[j] - En[j];
                u[j] = (d < -126 || Et[j] <= SENT) ? 0.0f
                     : __int_as_float(mb[j] | ((d + 127) << 23));
            }
            int E4_l1 = __shfl_up_sync(0xffffffffu, E4, 1); if (lane < 1) E4_l1 = SENT;
            int E3_l1 = __shfl_up_sync(0xffffffffu, E3, 1); if (lane < 1) E3_l1 = SENT;
            int Em1[NST] = {E4_l1, E0, E1, E2, E3};
            int Em2[NST] = {E3_l1, E4_l1, E0, E1, E2};
            float sb[NST], sc[NST];
#pragma unroll
            for (int j = 0; j < NST; ++j) {
                int db = min(Em1[j] - En[j], 126);
                sb[j] = (db < -126 || Em1[j] <= SENT) ? 0.0f : mkscale(db);
                int dc = min(Em2[j] - En[j], 126);
                float scv = (dc < -126 || Em2[j] <= SENT) ? 0.0f : mkscale(dc);
                sc[j] = skm[j] ? scv : 0.0f;
                Eb[j] = En[j];
            }
            // ---- 4 cheap steps ----
#pragma unroll
            for (int k = 0; k < RSTEPS; ++k) {
                int t = t0 + k;
                if (t <= tm) {
                    float vm1 = __shfl_up_sync(0xffffffffu, u[4], 1);
                    float vm2 = __shfl_up_sync(0xffffffffu, u[3], 1);
                    if (lane == 0) { vm1 = 0.0f; vm2 = 0.0f; }
                    float n0 = fmaf(vm2,  sc[0], fmaf(vm1,  sb[0], u[0])) * P[k][0];
                    float n1 = fmaf(vm1,  sc[1], fmaf(u[0], sb[1], u[1])) * P[k][1];
                    float n2 = fmaf(u[0], sc[2], fmaf(u[1], sb[2], u[2])) * P[k][2];
                    float n3 = fmaf(u[1], sc[3], fmaf(u[2], sb[3], u[3])) * P[k][3];
                    float n4 = fmaf(u[2], sc[4], fmaf(u[3], sb[4], u[4])) * P[k][4];
                    u[0] = n0; u[1] = n1; u[2] = n2; u[3] = n3; u[4] = n4;
                }
            }
            if (lane == 0) consF = tend;
        }
#pragma unroll
        for (int j = 0; j < NST; ++j) {
            int bits = __float_as_int(u[j]);
            int ex   = (bits >> 23) & 0xff;
            feF[lane * NST + j] = (ex == 0) ? SENT : (Eb[j] + ex - 127);
            fvF[lane * NST + j] = (ex == 0) ? 0.0f
                                : __int_as_float((bits & 0x007fffff) | 0x3f800000);
        }
    } else if (w == 1) {
        // ================= backward compute (gamma) =================
        int sk2m[NST];
#pragma unroll
        for (int j = 0; j < NST; ++j) {
            int s = lane * NST + j;
            int sk = 0;
            if ((s & 1) && (s + 2 <= L - 1)) {
                int lab  = tgt[s >> 1];
                int labp = tgt[(s >> 1) + 1];
                if (labp != 0 && labp != lab) sk = 1;
            }
            sk2m[j] = sk;
        }
        float u[NST]; int Eb[NST];
#pragma unroll
        for (int j = 0; j < NST; ++j) { u[j] = 0.0f; Eb[j] = SENT; }

        if (use_gamma) {
            int tl = tgt_len[b];
            int hi = 2 * tl; if (hi > L - 1) hi = L - 1;
            // init gamma at t = len-1
            {
                int* fp = &flgB[lenm1 & (RD - 1)];
                while (ld_acquire_cta(fp) != lenm1) { }
                const float* rp = &ringB[lenm1 & (RD - 1)][0];
#pragma unroll
                for (int j = 0; j < NST; ++j) {
                    int s = lane * NST + j;
                    if (tl > 0 && (s == hi || s == hi - 1)) {
                        u[j]  = rp[j * 32 + lane];
                        Eb[j] = 0;
                    }
                }
                if (lane == 0) consB = lenm1;
            }
            for (int t0 = lenm1 - 1; t0 >= tmp1; t0 -= RSTEPS) {
                int tlow = t0 - RSTEPS + 1; if (tlow < tmp1) tlow = tmp1;
#pragma unroll
                for (int k = 0; k < RSTEPS; ++k) {
                    int t = t0 - k;
                    if (t >= tmp1) {
                        int* fp = &flgB[t & (RD - 1)];
                        while (ld_acquire_cta(fp) != t) { }
                    }
                }
                float P[RSTEPS][NST];
#pragma unroll
                for (int k = 0; k < RSTEPS; ++k) {
                    int t = t0 - k; if (t < tmp1) t = tmp1;
                    const float* rp = &ringB[t & (RD - 1)][0];
#pragma unroll
                    for (int j = 0; j < NST; ++j) P[k][j] = rp[j * 32 + lane];
                }
                // ---- rebase (mirror window s..s+8) ----
                int Et[NST], mb[NST];
#pragma unroll
                for (int j = 0; j < NST; ++j) {
                    int bits = __float_as_int(u[j]);
                    int ex   = (bits >> 23) & 0xff;
                    Et[j] = (ex == 0) ? SENT : (Eb[j] + ex - 127);
                    mb[j] = bits & 0x007fffff;
                }
                int Pm1 = max(Et[0], Et[1]);
                int Pm2 = max(Pm1, Et[2]);
                int Pm3 = max(Pm2, Et[3]);
                int Pm4 = max(Pm3, Et[4]);
                int Sm4 = Et[4];
                int Sm3 = max(Et[3], Sm4);
                int Sm2 = max(Et[2], Sm3);
                int Sm1 = max(Et[1], Sm2);
                int Sm0 = max(Et[0], Sm1);
                int M_d1  = __shfl_down_sync(0xffffffffu, Pm4, 1);  if (lane > 30) M_d1  = SENT;
                int P3_d1 = __shfl_down_sync(0xffffffffu, Pm3, 1);  if (lane > 30) P3_d1 = SENT;
                int E0d2  = __shfl_down_sync(0xffffffffu, Et[0], 2); if (lane > 29) E0d2  = SENT;
                int P1_d2 = __shfl_down_sync(0xffffffffu, Pm1, 2);  if (lane > 29) P1_d2 = SENT;
                int P2_d2 = __shfl_down_sync(0xffffffffu, Pm2, 2);  if (lane > 29) P2_d2 = SENT;
                int E0 = max(Sm0, P3_d1);
                int E1 = max(Sm1, M_d1);
                int E2 = max(max(Sm2, M_d1), E0d2);
                int E3 = max(max(Sm3, M_d1), P1_d2);
                int E4 = max(max(Sm4, M_d1), P2_d2);
                int En[NST] = {E0, E1, E2, E3, E4};
#pragma unroll
                for (int j = 0; j < NST; ++j) {
                    int d = Et[j] - En[j];
                    u[j] = (d < -126 || Et[j] <= SENT) ? 0.0f
                         : __int_as_float(mb[j] | ((d + 127) << 23));
                }
                int E0_d1 = __shfl_down_sync(0xffffffffu, E0, 1); if (lane > 30) E0_d1 = SENT;
                int E1_d1 = __shfl_down_sync(0xffffffffu, E1, 1); if (lane > 30) E1_d1 = SENT;
                int Ep1[NST] = {E1, E2, E3, E4, E0_d1};
                int Ep2[NST] = {E2, E3, E4, E0_d1, E1_d1};
                float sb[NST], sc[NST];
#pragma unroll
                for (int j = 0; j < NST; ++j) {
                    int db = min(Ep1[j] - En[j], 126);
                    sb[j] = (db < -126 || Ep1[j] <= SENT) ? 0.0f : mkscale(db);
                    int dc = min(Ep2[j] - En[j], 126);
                    float scv = (dc < -126 || Ep2[j] <= SENT) ? 0.0f : mkscale(dc);
                    sc[j] = sk2m[j] ? scv : 0.0f;
                    Eb[j] = En[j];
                }
                // ---- 4 cheap steps (descending t) ----
#pragma unroll
                for (int k = 0; k < RSTEPS; ++k) {
                    int t = t0 - k;
                    if (t >= tmp1) {
                        float d0 = __shfl_down_sync(0xffffffffu, u[0], 1);
                        float d1 = __shfl_down_sync(0xffffffffu, u[1], 1);
                        if (lane == 31) { d0 = 0.0f; d1 = 0.0f; }
                        float n0 = fmaf(u[2], sc[0], fmaf(u[1], sb[0], u[0])) * P[k][0];
                        float n1 = fmaf(u[3], sc[1], fmaf(u[2], sb[1], u[1])) * P[k][1];
                        float n2 = fmaf(u[4], sc[2], fmaf(u[3], sb[2], u[2])) * P[k][2];
                        float n3 = fmaf(d0,   sc[3], fmaf(u[4], sb[3], u[3])) * P[k][3];
                        float n4 = fmaf(d1,   sc[4], fmaf(d0,   sb[4], u[4])) * P[k][4];
                        u[0] = n0; u[1] = n1; u[2] = n2; u[3] = n3; u[4] = n4;
                    }
                }
                if (lane == 0) consB = tlow;
            }
        }
#pragma unroll
        for (int j = 0; j < NST; ++j) {
            int bits = __float_as_int(u[j]);
            int ex   = (bits >> 23) & 0xff;
            feB[lane * NST + j] = (ex == 0) ? SENT : (Eb[j] + ex - 127);
            fvB[lane * NST + j] = (ex == 0) ? 0.0f
                                : __int_as_float((bits & 0x007fffff) | 0x3f800000);
        }
    } else {
        // ================= loader warps =================
        int lab2[NST];
#pragma unroll
        for (int j = 0; j < NST; ++j) {
            int s = lane * NST + j;
            int lab = 0;
            if (s < L && (s & 1)) lab = tgt[s >> 1];
            lab2[j] = lab;
        }
        const float* src = base + lane * 8;
        if (w < 5) {
            int i = w - 2;                    // forward loader 0..2
            int cnt = (tm >= 1 + i) ? ((tm - 1 - i) / 3 + 1) : 0;
            loader_warp(src, BC, 1 + i, cnt, 3, 1, max(tm, 1),
                        ringF, flgF, &consF, +1, &scratchA[i][0], lab2, lane);
        } else {
            int i = w - 5;                    // backward loader 0..2
            int start = lenm1 - i;
            int cnt = (start >= tmp1) ? ((start - tmp1) / 3 + 1) : 0;
            int lo = min(tmp1, lenm1); if (lo < 0) lo = 0;
            loader_warp(src, BC, start, cnt, -3, lo, lenm1,
                        ringB, flgB, &consB, -1, &scratchA[3 + i][0], lab2, lane);
        }
    }
    __syncthreads();

    // ================= combine: ll = sum_s alpha_tm[s] * beta_tm[s] =======
    if (w == 0) {
        int tl = tgt_len[b];
        int hi = 2 * tl; if (hi > L - 1) hi = L - 1;
        float Tv[NST]; int Te[NST];
#pragma unroll
        for (int j = 0; j < NST; ++j) { Tv[j] = 0.0f; Te[j] = SENT; }
        if (tl > 0) {
#pragma unroll
            for (int j = 0; j < NST; ++j) {
                int s = lane * NST + j;
                if (s < L) {
                    float va = fvF[s]; int ea = feF[s];
                    if (va != 0.0f) {
                        if (use_gamma) {
                            // beta_tm[s] = g[s] + g[s+1] + sk2[s]*g[s+2]
                            float g0v = fvB[s];     int g0e = feB[s];
                            float g1v = 0.0f;       int g1e = SENT;
                            float g2v = 0.0f;       int g2e = SENT;
                            if (s + 1 <= L - 1) { g1v = fvB[s + 1]; g1e = feB[s + 1]; }
                            int sk2 = 0;
                            if ((s & 1) && (s + 2 <= L - 1)) {
                                int lab  = tgt[s >> 1];
                                int labp = tgt[(s >> 1) + 1];
                                if (labp != 0 && labp != lab) sk2 = 1;
                            }
                            if (sk2) { g2v = fvB[s + 2]; g2e = feB[s + 2]; }
                            if (g0v == 0.0f) g0e = SENT;
                            if (g1v == 0.0f) g1e = SENT;
                            if (g2v == 0.0f) g2e = SENT;
                            int m = max(g0e, max(g1e, g2e));
                            if (m > SENT / 2) {
                                float bsum = 0.0f;
                                if (g0e > SENT / 2 && g0e - m >= -126) bsum += g0v * mkscale(g0e - m);
                                if (g1e > SENT / 2 && g1e - m >= -126) bsum += g1v * mkscale(g1e - m);
                                if (g2e > SENT / 2 && g2e - m >= -126) bsum += g2v * mkscale(g2e - m);
                                if (bsum > 0.0f) { Tv[j] = va * bsum; Te[j] = ea + m; }
                            }
                        } else {
                            if (s == hi || s == hi - 1) { Tv[j] = va; Te[j] = ea; }
                        }
                    }
                }
            }
        }
        int M = SENT;
#pragma unroll
        for (int j = 0; j < NST; ++j) if (Tv[j] > 0.0f) M = max(M, Te[j]);
#pragma unroll
        for (int o = 16; o > 0; o >>= 1)
            M = max(M, __shfl_xor_sync(0xffffffffu, M, o));
        double acc = 0.0;
#pragma unroll
        for (int j = 0; j < NST; ++j) {
            if (Tv[j] > 0.0f) {
                long long d = (long long)Te[j] - M;
                if (d > -1000) {
                    unsigned long long bits2 = (unsigned long long)(d + 1023) << 52;
                    acc += (double)Tv[j] * __longlong_as_double((long long)bits2);
                }
            }
        }
#pragma unroll
        for (int o = 16; o > 0; o >>= 1)
            acc += __shfl_xor_sync(0xffffffffu, acc, o);
        if (lane == 0) {
            float loss = 0.0f;
            if (tl > 0 && acc > 0.0 && M > SENT / 2) {
                double ll = ((double)M + log2(acc)) * 0.69314718055994530942;
                loss = (float)(-ll / (double)tl);
            }
            g_loss[b] = loss;
            __threadfence();
            unsigned old = atomicAdd(&g_cnt, 1);
            s_last = (old == (unsigned)(gridDim.x - 1)) ? 1 : 0;
        }
    }
    __syncthreads();

    // ---- last CTA: fused mean reduction ----
    if (s_last) {
        __threadfence();
        float acc2 = 0.0f;
        for (int i2 = tid; i2 < B; i2 += 256) acc2 += g_loss[i2];
#pragma unroll
        for (int o = 16; o > 0; o >>= 1)
            acc2 += __shfl_xor_sync(0xffffffffu, acc2, o);
        if (lane == 0) red[w] = acc2;
        __syncthreads();
        if (tid == 0) {
            float s8 = 0.0f;
#pragma unroll
            for (int k = 0; k < 8; ++k) s8 += red[k];
            out[0] = s8 / (float)B;
            g_cnt = 0;   // reset for next graph replay
        }
    }
}

extern "C" void kernel_launch(void* const* d_in, const int* in_sizes, int n_in,
                              void* d_out, int out_size)
{
    const float* logp    = (const float*)d_in[0];
    const int*   targets = (const int*)d_in[1];
    const int*   in_len  = (const int*)d_in[2];
    const int*   tgt_len = (const int*)d_in[3];

    int B = in_sizes[2];                                   // 128
    int S = in_sizes[1] / B;                               // 64
    int C = 256;
    int T = (int)((size_t)in_sizes[0] / ((size_t)B * C));  // 1024

    ctc_bisect_kernel<<<B, 256>>>(logp, targets, in_len, tgt_len,
                                  (float*)d_out, T, B, C, S);
}

// round 10
// speedup vs baseline: 3.2492x; 1.3113x over previous
#include <cuda_runtime.h>

// CTC loss, bisected forward/backward with warp-specialized loaders.
// 256 thr/CTA: w0 fwd compute, w1 bwd compute, w2-4 fwd loaders, w5-7 bwd.
// Extended-range alpha[s] = u[s]*2^Eb[s], block-rebased every RSTEPS=8 steps.
// Loaders: static-indexed LDG pipeline, exp only gathered states, publish via
// per-loader monotone progress counters (st.release / ld.acquire).
// All float4-accessed shared arrays are explicitly 16B-aligned.

#define NST    5
#define RSTEPS 8
#define RD     32          // ring rows per direction (power of 2)
#define LEAD   24          // loader may lead consumed row by < LEAD
#define DEPTH  6           // loader LDG pipeline depth (static stages)
#define SENT   (-(1 << 28))

__device__ float    g_loss[1024];
__device__ unsigned g_cnt = 0;

__device__ __forceinline__ void st_release_cta(int* p, int v) {
    asm volatile("st.release.cta.b32 [%0], %1;" :: "l"(p), "r"(v) : "memory");
}
__device__ __forceinline__ int ld_acquire_cta(const int* p) {
    int v;
    asm volatile("ld.acquire.cta.b32 %0, [%1];" : "=r"(v) : "l"(p) : "memory");
    return v;
}
__device__ __forceinline__ int iclamp(int x, int lo, int hi) {
    return min(max(x, lo), hi);
}
__device__ __forceinline__ float mkscale(int d) {   // 2^d, d in [-126,126]
    return __int_as_float((d + 127) << 23);
}

// Loader: stream rows t_begin, +stride... (cnt rows); stage raw row in
// scratch; gather per-state log-probs; exp; store to ring; release progress.
__device__ __forceinline__ void loader_warp(
    const float* src, size_t BC,
    int t_begin, int cnt, int stride, int lo, int hi,
    float (*ring)[NST * 32], int* progP,
    volatile int* consP, int consSign,
    float* scratch, const int* lab2, int lane)
{
    float4 Aa[DEPTH], Ab[DEPTH];
    int tq = t_begin;
#pragma unroll
    for (int k = 0; k < DEPTH; ++k) {
        int tt = iclamp(tq, lo, hi);
        const float* r = src + (size_t)tt * BC;
        Aa[k] = *(const float4*)r;
        Ab[k] = *(const float4*)(r + 4);
        tq += stride;
    }
    int t = t_begin;
    int consv = *consP;
    const int c0 = lane * 8;
    while (cnt > 0) {
#pragma unroll
        for (int k = 0; k < DEPTH; ++k) {
            if (cnt > 0) {
                for (;;) {                       // backpressure
                    int lead = (consSign > 0) ? (t - consv) : (consv - t);
                    if (lead < LEAD) break;
                    __nanosleep(20);
                    consv = *consP;
                }
                float* scr = scratch + c0;
                ((float4*)scr)[0] = Aa[k];       // raw row stage
                ((float4*)scr)[1] = Ab[k];
                __syncwarp();
                float* dst = ring[t & (RD - 1)];
#pragma unroll
                for (int j = 0; j < NST; ++j)
                    dst[j * 32 + lane] = __expf(scratch[lab2[j]]);
                __syncwarp();
                if (lane == 0) st_release_cta(progP, t);
                int tt = iclamp(tq, lo, hi);     // refill stage k (static)
                const float* r = src + (size_t)tt * BC;
                Aa[k] = *(const float4*)r;
                Ab[k] = *(const float4*)(r + 4);
                tq += stride;
                t += stride;
                --cnt;
            }
        }
    }
    __syncwarp();
    if (lane == 0)                               // terminal: never block consumer
        st_release_cta(progP, (consSign > 0) ? 0x3fffffff : -0x3fffffff);
}

__global__ void __launch_bounds__(256, 1)
ctc_bisect2_kernel(const float* __restrict__ logp,
                   const int*   __restrict__ targets,
                   const int*   __restrict__ in_len,
                   const int*   __restrict__ tgt_len,
                   float*       __restrict__ out,
                   int T, int B, int C, int S)
{
    const int b    = blockIdx.x;
    const int tid  = threadIdx.x;
    const int w    = tid >> 5;
    const int lane = tid & 31;
    const int L    = 2 * S + 1;
    const int* tgt = targets + (size_t)b * S;

    __shared__ __align__(16) float ringF[RD][NST * 32];
    __shared__ __align__(16) float ringB[RD][NST * 32];
    __shared__ __align__(16) float scratchA[6][256];
    __shared__ int          progF[3], progB[3];
    __shared__ volatile int consF, consB;
    __shared__ float        fvF[NST * 32]; __shared__ int feF[NST * 32];
    __shared__ float        fvB[NST * 32]; __shared__ int feB[NST * 32];
    __shared__ float        red[8];
    __shared__ int          s_last;

    const size_t BC   = (size_t)B * C;
    const float* base = logp + (size_t)b * C;

    int len = in_len[b];
    if (len > T) len = T;
    if (len < 1) len = 1;
    const int lenm1 = len - 1;
    const int tm    = lenm1 >> 1;
    const int tmp1  = tm + 1;
    const bool use_gamma = (lenm1 > tm);

    if (tid == 0) { consF = 0; consB = len; }
    if (tid < 3) { progF[tid] = 0; progB[tid] = len + 8; }
    __syncthreads();

    if (w == 0) {
        // ================= forward compute (alpha) =================
        int skm[NST];
#pragma unroll
        for (int j = 0; j < NST; ++j) {
            int s = lane * NST + j;
            int sk = 0;
            if (s < L && s >= 3 && (s & 1)) {
                int lab = tgt[s >> 1];
                int lm2 = tgt[(s - 2) >> 1];
                if (lab != 0 && lab != lm2) sk = 1;
            }
            skm[j] = sk;
        }
        float u[NST]; int Eb[NST];
#pragma unroll
        for (int j = 0; j < NST; ++j) { u[j] = 0.0f; Eb[j] = SENT; }
        if (lane == 0) {
            float y0 = __ldg(base) * 1.4426950408889634f;
            float f0 = floorf(y0); Eb[0] = (int)f0; u[0] = exp2f(y0 - f0);
            if (L > 1) {
                int lab1 = tgt[0];
                float y1 = __ldg(base + lab1) * 1.4426950408889634f;
                float f1 = floorf(y1); Eb[1] = (int)f1; u[1] = exp2f(y1 - f1);
            }
        }

        int mnF = 0;
        for (int t0 = 1; t0 <= tm; t0 += RSTEPS) {
            int tend = t0 + RSTEPS - 1; if (tend > tm) tend = tm;
            if (mnF < tend) {
                do {
                    int a0 = ld_acquire_cta(&progF[0]);
                    int a1 = ld_acquire_cta(&progF[1]);
                    int a2 = ld_acquire_cta(&progF[2]);
                    mnF = min(a0, min(a1, a2));
                } while (mnF < tend);
            }
            float P[RSTEPS][NST];
#pragma unroll
            for (int k = 0; k < RSTEPS; ++k) {
                int t = t0 + k; if (t > tm) t = tm;
                const float* rp = &ringF[t & (RD - 1)][0];
#pragma unroll
                for (int j = 0; j < NST; ++j) P[k][j] = rp[j * 32 + lane];
            }
            // ---- rebase: E'[s] = max(Et[s-16..s]) ----
            int Et[NST], mb[NST];
#pragma unroll
            for (int j = 0; j < NST; ++j) {
                int bits = __float_as_int(u[j]);
                int ex   = (bits >> 23) & 0xff;
                Et[j] = (ex == 0) ? SENT : (Eb[j] + ex - 127);
                mb[j] = bits & 0x007fffff;
            }
            int P0 = Et[0];
            int P1 = max(P0, Et[1]);
            int P2 = max(P1, Et[2]);
            int P3 = max(P2, Et[3]);
            int P4 = max(P3, Et[4]);
            int S4 = Et[4];
            int S3 = max(Et[3], S4);
            int S2 = max(Et[2], S3);
            int S1 = max(Et[1], S2);
            int Mm1  = __shfl_up_sync(0xffffffffu, P4, 1);    if (lane < 1) Mm1  = SENT;
            int Mm2  = __shfl_up_sync(0xffffffffu, P4, 2);    if (lane < 2) Mm2  = SENT;
            int Mm3  = __shfl_up_sync(0xffffffffu, P4, 3);    if (lane < 3) Mm3  = SENT;
            int S1m3 = __shfl_up_sync(0xffffffffu, S1, 3);    if (lane < 3) S1m3 = SENT;
            int S2m3 = __shfl_up_sync(0xffffffffu, S2, 3);    if (lane < 3) S2m3 = SENT;
            int S3m3 = __shfl_up_sync(0xffffffffu, S3, 3);    if (lane < 3) S3m3 = SENT;
            int E4m4 = __shfl_up_sync(0xffffffffu, Et[4], 4); if (lane < 4) E4m4 = SENT;
            int M12 = max(Mm1, Mm2);
            int E0 = max(max(P0, M12), max(Mm3, E4m4));
            int E1 = max(max(P1, M12), Mm3);
            int E2 = max(max(P2, M12), S1m3);
            int E3 = max(max(P3, M12), S2m3);
            int E4 = max(max(P4, M12), S3m3);
            int En[NST] = {E0, E1, E2, E3, E4};
#pragma unroll
            for (int j = 0; j < NST; ++j) {
                int d = Et[j] - En[j];
                u[j] = (d < -126 || Et[j] <= SENT) ? 0.0f
                     : __int_as_float(mb[j] | ((d + 127) << 23));
            }
            int E4m1 = __shfl_up_sync(0xffffffffu, E4, 1); if (lane < 1) E4m1 = SENT;
            int E3m1 = __shfl_up_sync(0xffffffffu, E3, 1); if (lane < 1) E3m1 = SENT;
            int Em1[NST] = {E4m1, E0, E1, E2, E3};
            int Em2[NST] = {E3m1, E4m1, E0, E1, E2};
            float sb[NST], sc[NST];
#pragma unroll
            for (int j = 0; j < NST; ++j) {
                int db = min(Em1[j] - En[j], 126);
                sb[j] = (db < -126 || Em1[j] <= SENT) ? 0.0f : mkscale(db);
                int dc = min(Em2[j] - En[j], 126);
                float scv = (dc < -126 || Em2[j] <= SENT) ? 0.0f : mkscale(dc);
                sc[j] = skm[j] ? scv : 0.0f;
                Eb[j] = En[j];
            }
            // ---- 8 cheap steps ----
#pragma unroll
            for (int k = 0; k < RSTEPS; ++k) {
                int t = t0 + k;
                if (t <= tm) {
                    float vm1 = __shfl_up_sync(0xffffffffu, u[4], 1);
                    float vm2 = __shfl_up_sync(0xffffffffu, u[3], 1);
                    if (lane == 0) { vm1 = 0.0f; vm2 = 0.0f; }
                    float n0 = fmaf(vm2,  sc[0], fmaf(vm1,  sb[0], u[0])) * P[k][0];
                    float n1 = fmaf(vm1,  sc[1], fmaf(u[0], sb[1], u[1])) * P[k][1];
                    float n2 = fmaf(u[0], sc[2], fmaf(u[1], sb[2], u[2])) * P[k][2];
                    float n3 = fmaf(u[1], sc[3], fmaf(u[2], sb[3], u[3])) * P[k][3];
                    float n4 = fmaf(u[2], sc[4], fmaf(u[3], sb[4], u[4])) * P[k][4];
                    u[0] = n0; u[1] = n1; u[2] = n2; u[3] = n3; u[4] = n4;
                }
            }
            if (lane == 0) consF = tend;
        }
#pragma unroll
        for (int j = 0; j < NST; ++j) {
            int bits = __float_as_int(u[j]);
            int ex   = (bits >> 23) & 0xff;
            feF[lane * NST + j] = (ex == 0) ? SENT : (Eb[j] + ex - 127);
            fvF[lane * NST + j] = (ex == 0) ? 0.0f
                                : __int_as_float((bits & 0x007fffff) | 0x3f800000);
        }
    } else if (w == 1) {
        // ================= backward compute (gamma) =================
        int sk2m[NST];
#pragma unroll
        for (int j = 0; j < NST; ++j) {
            int s = lane * NST + j;
            int sk = 0;
            if ((s & 1) && (s + 2 <= L - 1)) {
                int lab  = tgt[s >> 1];
                int labp = tgt[(s >> 1) + 1];
                if (labp != 0 && labp != lab) sk = 1;
            }
            sk2m[j] = sk;
        }
        float u[NST]; int Eb[NST];
#pragma unroll
        for (int j = 0; j < NST; ++j) { u[j] = 0.0f; Eb[j] = SENT; }

        if (use_gamma) {
            int tl = tgt_len[b];
            int hi = 2 * tl; if (hi > L - 1) hi = L - 1;
            // init gamma at t = len-1
            {
                int mx;
                do {
                    int a0 = ld_acquire_cta(&progB[0]);
                    int a1 = ld_acquire_cta(&progB[1]);
                    int a2 = ld_acquire_cta(&progB[2]);
                    mx = max(a0, max(a1, a2));
                } while (mx > lenm1);
                const float* rp = &ringB[lenm1 & (RD - 1)][0];
#pragma unroll
                for (int j = 0; j < NST; ++j) {
                    int s = lane * NST + j;
                    if (tl > 0 && (s == hi || s == hi - 1)) {
                        u[j]  = rp[j * 32 + lane];
                        Eb[j] = 0;
                    }
                }
                if (lane == 0) consB = lenm1;
            }
            int mxB = lenm1;
            for (int t0 = lenm1 - 1; t0 >= tmp1; t0 -= RSTEPS) {
                int tlow = t0 - RSTEPS + 1; if (tlow < tmp1) tlow = tmp1;
                if (mxB > tlow) {
                    do {
                        int a0 = ld_acquire_cta(&progB[0]);
                        int a1 = ld_acquire_cta(&progB[1]);
                        int a2 = ld_acquire_cta(&progB[2]);
                        mxB = max(a0, max(a1, a2));
                    } while (mxB > tlow);
                }
                float P[RSTEPS][NST];
#pragma unroll
                for (int k = 0; k < RSTEPS; ++k) {
                    int t = t0 - k; if (t < tmp1) t = tmp1;
                    const float* rp = &ringB[t & (RD - 1)][0];
#pragma unroll
                    for (int j = 0; j < NST; ++j) P[k][j] = rp[j * 32 + lane];
                }
                // ---- rebase: E'[s] = max(Et[s..s+16]) ----
                int Et[NST], mb[NST];
#pragma unroll
                for (int j = 0; j < NST; ++j) {
                    int bits = __float_as_int(u[j]);
                    int ex   = (bits >> 23) & 0xff;
                    Et[j] = (ex == 0) ? SENT : (Eb[j] + ex - 127);
                    mb[j] = bits & 0x007fffff;
                }
                int Pm1 = max(Et[0], Et[1]);
                int Pm2 = max(Pm1, Et[2]);
                int Pm3 = max(Pm2, Et[3]);
                int M   = max(Pm3, Et[4]);
                int Sm4 = Et[4];
                int Sm3 = max(Et[3], Sm4);
                int Sm2 = max(Et[2], Sm3);
                int Sm1 = max(Et[1], Sm2);
                int Sm0 = max(Et[0], Sm1);
                int Mp1  = __shfl_down_sync(0xffffffffu, M, 1);     if (lane > 30) Mp1  = SENT;
                int Mp2  = __shfl_down_sync(0xffffffffu, M, 2);     if (lane > 29) Mp2  = SENT;
                int Mp3  = __shfl_down_sync(0xffffffffu, M, 3);     if (lane > 28) Mp3  = SENT;
                int P1p3 = __shfl_down_sync(0xffffffffu, Pm1, 3);   if (lane > 28) P1p3 = SENT;
                int P2p3 = __shfl_down_sync(0xffffffffu, Pm2, 3);   if (lane > 28) P2p3 = SENT;
                int P3p3 = __shfl_down_sync(0xffffffffu, Pm3, 3);   if (lane > 28) P3p3 = SENT;
                int E0p4 = __shfl_down_sync(0xffffffffu, Et[0], 4); if (lane > 27) E0p4 = SENT;
                int M12 = max(Mp1, Mp2);
                int E0 = max(max(Sm0, M12), P1p3);
                int E1 = max(max(Sm1, M12), P2p3);
                int E2 = max(max(Sm2, M12), P3p3);
                int E3 = max(max(Sm3, M12), Mp3);
                int E4 = max(max(Sm4, M12), max(Mp3, E0p4));
                int En[NST] = {E0, E1, E2, E3, E4};
#pragma unroll
                for (int j = 0; j < NST; ++j) {
                    int d = Et[j] - En[j];
                    u[j] = (d < -126 || Et[j] <= SENT) ? 0.0f
                         : __int_as_float(mb[j] | ((d + 127) << 23));
                }
                int E0p1 = __shfl_down_sync(0xffffffffu, E0, 1); if (lane > 30) E0p1 = SENT;
                int E1p1 = __shfl_down_sync(0xffffffffu, E1, 1); if (lane > 30) E1p1 = SENT;
                int Ep1[NST] = {E1, E2, E3, E4, E0p1};
                int Ep2[NST] = {E2, E3, E4, E0p1, E1p1};
                float sb[NST], sc[NST];
#pragma unroll
                for (int j = 0; j < NST; ++j) {
                    int db = min(Ep1[j] - En[j], 126);
                    sb[j] = (db < -126 || Ep1[j] <= SENT) ? 0.0f : mkscale(db);
                    int dc = min(Ep2[j] - En[j], 126);
                    float scv = (dc < -126 || Ep2[j] <= SENT) ? 0.0f : mkscale(dc);
                    sc[j] = sk2m[j] ? scv : 0.0f;
                    Eb[j] = En[j];
                }
                // ---- 8 cheap steps (descending t) ----
#pragma unroll
                for (int k = 0; k < RSTEPS; ++k) {
                    int t = t0 - k;
                    if (t >= tmp1) {
                        float d0 = __shfl_down_sync(0xffffffffu, u[0], 1);
                        float d1 = __shfl_down_sync(0xffffffffu, u[1], 1);
                        if (lane == 31) { d0 = 0.0f; d1 = 0.0f; }
                        float n0 = fmaf(u[2], sc[0], fmaf(u[1], sb[0], u[0])) * P[k][0];
                        float n1 = fmaf(u[3], sc[1], fmaf(u[2], sb[1], u[1])) * P[k][1];
                        float n2 = fmaf(u[4], sc[2], fmaf(u[3], sb[2], u[2])) * P[k][2];
                        float n3 = fmaf(d0,   sc[3], fmaf(u[4], sb[3], u[3])) * P[k][3];
                        float n4 = fmaf(d1,   sc[4], fmaf(d0,   sb[4], u[4])) * P[k][4];
                        u[0] = n0; u[1] = n1; u[2] = n2; u[3] = n3; u[4] = n4;
                    }
                }
                if (lane == 0) consB = tlow;
            }
        }
#pragma unroll
        for (int j = 0; j < NST; ++j) {
            int bits = __float_as_int(u[j]);
            int ex   = (bits >> 23) & 0xff;
            feB[lane * NST + j] = (ex == 0) ? SENT : (Eb[j] + ex - 127);
            fvB[lane * NST + j] = (ex == 0) ? 0.0f
                                : __int_as_float((bits & 0x007fffff) | 0x3f800000);
        }
    } else {
        // ================= loader warps =================
        int lab2[NST];
#pragma unroll
        for (int j = 0; j < NST; ++j) {
            int s = lane * NST + j;
            int lab = 0;
            if (s < L && (s & 1)) lab = tgt[s >> 1];
            lab2[j] = lab;
        }
        const float* src = base + lane * 8;
        if (w < 5) {
            int i = w - 2;
            int cnt = (tm >= 1 + i) ? ((tm - 1 - i) / 3 + 1) : 0;
            loader_warp(src, BC, 1 + i, cnt, 3, 1, max(tm, 1),
                        ringF, &progF[i], &consF, +1, &scratchA[i][0], lab2, lane);
        } else {
            int i = w - 5;
            int start = lenm1 - i;
            int cnt = (start >= tmp1) ? ((start - tmp1) / 3 + 1) : 0;
            int lo = min(tmp1, lenm1); if (lo < 0) lo = 0;
            loader_warp(src, BC, start, cnt, -3, lo, lenm1,
                        ringB, &progB[i], &consB, -1, &scratchA[3 + i][0], lab2, lane);
        }
    }
    __syncthreads();

    // ================= combine: ll = sum_s alpha_tm[s] * beta_tm[s] =======
    if (w == 0) {
        int tl = tgt_len[b];
        int hi = 2 * tl; if (hi > L - 1) hi = L - 1;
        float Tv[NST]; int Te[NST];
#pragma unroll
        for (int j = 0; j < NST; ++j) { Tv[j] = 0.0f; Te[j] = SENT; }
        if (tl > 0) {
#pragma unroll
            for (int j = 0; j < NST; ++j) {
                int s = lane * NST + j;
                if (s < L) {
                    float va = fvF[s]; int ea = feF[s];
                    if (va != 0.0f) {
                        if (use_gamma) {
                            float g0v = fvB[s];     int g0e = feB[s];
                            float g1v = 0.0f;       int g1e = SENT;
                            float g2v = 0.0f;       int g2e = SENT;
                            if (s + 1 <= L - 1) { g1v = fvB[s + 1]; g1e = feB[s + 1]; }
                            int sk2 = 0;
                            if ((s & 1) && (s + 2 <= L - 1)) {
                                int lab  = tgt[s >> 1];
                                int labp = tgt[(s >> 1) + 1];
                                if (labp != 0 && labp != lab) sk2 = 1;
                            }
                            if (sk2) { g2v = fvB[s + 2]; g2e = feB[s + 2]; }
                            if (g0v == 0.0f) g0e = SENT;
                            if (g1v == 0.0f) g1e = SENT;
                            if (g2v == 0.0f) g2e = SENT;
                            int m = max(g0e, max(g1e, g2e));
                            if (m > SENT / 2) {
                                float bsum = 0.0f;
                                if (g0e > SENT / 2 && g0e - m >= -126) bsum += g0v * mkscale(g0e - m);
                                if (g1e > SENT / 2 && g1e - m >= -126) bsum += g1v * mkscale(g1e - m);
                                if (g2e > SENT / 2 && g2e - m >= -126) bsum += g2v * mkscale(g2e - m);
                                if (bsum > 0.0f) { Tv[j] = va * bsum; Te[j] = ea + m; }
                            }
                        } else {
                            if (s == hi || s == hi - 1) { Tv[j] = va; Te[j] = ea; }
                        }
                    }
                }
            }
        }
        int M = SENT;
#pragma unroll
        for (int j = 0; j < NST; ++j) if (Tv[j] > 0.0f) M = max(M, Te[j]);
#pragma unroll
        for (int o = 16; o > 0; o >>= 1)
            M = max(M, __shfl_xor_sync(0xffffffffu, M, o));
        double acc = 0.0;
#pragma unroll
        for (int j = 0; j < NST; ++j) {
            if (Tv[j] > 0.0f) {
                long long d = (long long)Te[j] - M;
                if (d > -1000) {
                    unsigned long long bits2 = (unsigned long long)(d + 1023) << 52;
                    acc += (double)Tv[j] * __longlong_as_double((long long)bits2);
                }
            }
        }
#pragma unroll
        for (int o = 16; o > 0; o >>= 1)
            acc += __shfl_xor_sync(0xffffffffu, acc, o);
        if (lane == 0) {
            float loss = 0.0f;
            if (tl > 0 && acc > 0.0 && M > SENT / 2) {
                double ll = ((double)M + log2(acc)) * 0.69314718055994530942;
                loss = (float)(-ll / (double)tl);
            }
            g_loss[b] = loss;
            __threadfence();
            unsigned old = atomicAdd(&g_cnt, 1);
            s_last = (old == (unsigned)(gridDim.x - 1)) ? 1 : 0;
        }
    }
    __syncthreads();

    // ---- last CTA: fused mean reduction ----
    if (s_last) {
        __threadfence();
        float acc2 = 0.0f;
        for (int i2 = tid; i2 < B; i2 += 256) acc2 += g_loss[i2];
#pragma unroll
        for (int o = 16; o > 0; o >>= 1)
            acc2 += __shfl_xor_sync(0xffffffffu, acc2, o);
        if (lane == 0) red[w] = acc2;
        __syncthreads();
        if (tid == 0) {
            float s8 = 0.0f;
#pragma unroll
            for (int k = 0; k < 8; ++k) s8 += red[k];
            out[0] = s8 / (float)B;
            g_cnt = 0;   // reset for next graph replay
        }
    }
}

extern "C" void kernel_launch(void* const* d_in, const int* in_sizes, int n_in,
                              void* d_out, int out_size)
{
    const float* logp    = (const float*)d_in[0];
    const int*   targets = (const int*)d_in[1];
    const int*   in_len  = (const int*)d_in[2];
    const int*   tgt_len = (const int*)d_in[3];

    int B = in_sizes[2];                                   // 128
    int S = in_sizes[1] / B;                               // 64
    int C = 256;
    int T = (int)((size_t)in_sizes[0] / ((size_t)B * C));  // 1024

    ctc_bisect2_kernel<<<B, 256>>>(logp, targets, in_len, tgt_len,
                                   (float*)d_out, T, B, C, S);
}

// round 11
// speedup vs baseline: 3.8265x; 1.1777x over previous
#include <cuda_runtime.h>

// CTC loss. Two CTAs per batch element: dir 0 = forward alpha over t=1..tm,
// dir 1 = backward gamma over t=len-1..tm+1. Each CTA: 1 compute warp +
// 7 loader warps (static-indexed LDG pipeline, exp on gathered states only,
// monotone per-loader progress counters). Extended-range u*2^E arithmetic,
// block-rebased every RSTEPS=8 steps. Halves meet through global scratch;
// second-arriving CTA of each pair combines ll = sum_s alpha_tm[s]*beta_tm[s].

#define NST    5
#define RSTEPS 8
#define RD     32          // ring rows (power of 2)
#define LEAD   24          // loader lead bound (< RD - 8)
#define DEPTH  6           // loader LDG pipeline depth (static stages)
#define NLD    7           // loader warps per CTA
#define SENT   (-(1 << 28))

__device__ float    g_loss[1024];
__device__ unsigned g_cnt = 0;
__device__ int      g_pair[1024];                 // zero-init
__device__ float    g_fv[2][1024][NST * 32];
__device__ int      g_fe[2][1024][NST * 32];

__device__ __forceinline__ void st_release_cta(int* p, int v) {
    asm volatile("st.release.cta.b32 [%0], %1;" :: "l"(p), "r"(v) : "memory");
}
__device__ __forceinline__ int ld_acquire_cta(const int* p) {
    int v;
    asm volatile("ld.acquire.cta.b32 %0, [%1];" : "=r"(v) : "l"(p) : "memory");
    return v;
}
__device__ __forceinline__ int iclamp(int x, int lo, int hi) {
    return min(max(x, lo), hi);
}
__device__ __forceinline__ float mkscale(int d) {   // 2^d, d in [-126,126]
    return __int_as_float((d + 127) << 23);
}

__device__ __forceinline__ void loader_warp(
    const float* src, size_t BC,
    int t_begin, int cnt, int stride, int lo, int hi,
    float (*ring)[NST * 32], int* progP,
    volatile int* consP, int consSign,
    float* scratch, const int* lab2, int lane)
{
    float4 Aa[DEPTH], Ab[DEPTH];
    int tq = t_begin;
#pragma unroll
    for (int k = 0; k < DEPTH; ++k) {
        int tt = iclamp(tq, lo, hi);
        const float* r = src + (size_t)tt * BC;
        Aa[k] = *(const float4*)r;
        Ab[k] = *(const float4*)(r + 4);
        tq += stride;
    }
    int t = t_begin;
    int consv = *consP;
    const int c0 = lane * 8;
    while (cnt > 0) {
#pragma unroll
        for (int k = 0; k < DEPTH; ++k) {
            if (cnt > 0) {
                for (;;) {
                    int lead = (consSign > 0) ? (t - consv) : (consv - t);
                    if (lead < LEAD) break;
                    __nanosleep(20);
                    consv = *consP;
                }
                float* scr = scratch + c0;
                ((float4*)scr)[0] = Aa[k];
                ((float4*)scr)[1] = Ab[k];
                __syncwarp();
                float* dst = ring[t & (RD - 1)];
#pragma unroll
                for (int j = 0; j < NST; ++j)
                    dst[j * 32 + lane] = __expf(scratch[lab2[j]]);
                __syncwarp();
                if (lane == 0) st_release_cta(progP, t);
                int tt = iclamp(tq, lo, hi);
                const float* r = src + (size_t)tt * BC;
                Aa[k] = *(const float4*)r;
                Ab[k] = *(const float4*)(r + 4);
                tq += stride;
                t += stride;
                --cnt;
            }
        }
    }
    __syncwarp();
    if (lane == 0)
        st_release_cta(progP, (consSign > 0) ? 0x3fffffff : -0x3fffffff);
}

__global__ void __launch_bounds__(256, 2)
ctc_split_kernel(const float* __restrict__ logp,
                 const int*   __restrict__ targets,
                 const int*   __restrict__ in_len,
                 const int*   __restrict__ tgt_len,
                 float*       __restrict__ out,
                 int T, int B, int C, int S)
{
    const int b    = blockIdx.x >> 1;
    const int dir  = blockIdx.x & 1;
    const int tid  = threadIdx.x;
    const int w    = tid >> 5;
    const int lane = tid & 31;
    const int L    = 2 * S + 1;
    const int* tgt = targets + (size_t)b * S;

    __shared__ __align__(16) float ring[RD][NST * 32];
    __shared__ __align__(16) float scratchA[NLD][256];
    __shared__ int          prog[NLD];
    __shared__ volatile int cons;
    __shared__ float        red[8];
    __shared__ int          s_flags;    // bit0: do combine; bit1: last

    const size_t BC   = (size_t)B * C;
    const float* base = logp + (size_t)b * C;

    int len = in_len[b];
    if (len > T) len = T;
    if (len < 1) len = 1;
    const int lenm1 = len - 1;
    const int tm    = lenm1 >> 1;
    const int tmp1  = tm + 1;
    const bool use_gamma = (lenm1 > tm);

    if (tid == 0) { cons = dir ? len : 0; s_flags = 0; }
    if (tid < NLD) prog[tid] = dir ? (len + 8) : 0;
    __syncthreads();

    float* outv = &g_fv[dir][b][0];
    int*   oute = &g_fe[dir][b][0];

    if (w == 0 && dir == 0) {
        // ================= forward compute (alpha) =================
        int skm[NST];
#pragma unroll
        for (int j = 0; j < NST; ++j) {
            int s = lane * NST + j;
            int sk = 0;
            if (s < L && s >= 3 && (s & 1)) {
                int lab = tgt[s >> 1];
                int lm2 = tgt[(s - 2) >> 1];
                if (lab != 0 && lab != lm2) sk = 1;
            }
            skm[j] = sk;
        }
        float u[NST]; int Eb[NST];
#pragma unroll
        for (int j = 0; j < NST; ++j) { u[j] = 0.0f; Eb[j] = SENT; }
        if (lane == 0) {
            float y0 = __ldg(base) * 1.4426950408889634f;
            float f0 = floorf(y0); Eb[0] = (int)f0; u[0] = exp2f(y0 - f0);
            if (L > 1) {
                int lab1 = tgt[0];
                float y1 = __ldg(base + lab1) * 1.4426950408889634f;
                float f1 = floorf(y1); Eb[1] = (int)f1; u[1] = exp2f(y1 - f1);
            }
        }

        int mn = 0;
        for (int t0 = 1; t0 <= tm; t0 += RSTEPS) {
            int tend = t0 + RSTEPS - 1; if (tend > tm) tend = tm;
            if (mn < tend) {
                do {
                    mn = ld_acquire_cta(&prog[0]);
#pragma unroll
                    for (int q = 1; q < NLD; ++q)
                        mn = min(mn, ld_acquire_cta(&prog[q]));
                } while (mn < tend);
            }
            float P[RSTEPS][NST];
#pragma unroll
            for (int k = 0; k < RSTEPS; ++k) {
                int t = t0 + k; if (t > tm) t = tm;
                const float* rp = &ring[t & (RD - 1)][0];
#pragma unroll
                for (int j = 0; j < NST; ++j) P[k][j] = rp[j * 32 + lane];
            }
            // rebase: E'[s] = max(Et[s-16..s])
            int Et[NST], mb[NST];
#pragma unroll
            for (int j = 0; j < NST; ++j) {
                int bits = __float_as_int(u[j]);
                int ex   = (bits >> 23) & 0xff;
                Et[j] = (ex == 0) ? SENT : (Eb[j] + ex - 127);
                mb[j] = bits & 0x007fffff;
            }
            int P0 = Et[0];
            int P1 = max(P0, Et[1]);
            int P2 = max(P1, Et[2]);
            int P3 = max(P2, Et[3]);
            int P4 = max(P3, Et[4]);
            int S4 = Et[4];
            int S3 = max(Et[3], S4);
            int S2 = max(Et[2], S3);
            int S1 = max(Et[1], S2);
            int Mm1  = __shfl_up_sync(0xffffffffu, P4, 1);    if (lane < 1) Mm1  = SENT;
            int Mm2  = __shfl_up_sync(0xffffffffu, P4, 2);    if (lane < 2) Mm2  = SENT;
            int Mm3  = __shfl_up_sync(0xffffffffu, P4, 3);    if (lane < 3) Mm3  = SENT;
            int S1m3 = __shfl_up_sync(0xffffffffu, S1, 3);    if (lane < 3) S1m3 = SENT;
            int S2m3 = __shfl_up_sync(0xffffffffu, S2, 3);    if (lane < 3) S2m3 = SENT;
            int S3m3 = __shfl_up_sync(0xffffffffu, S3, 3);    if (lane < 3) S3m3 = SENT;
            int E4m4 = __shfl_up_sync(0xffffffffu, Et[4], 4); if (lane < 4) E4m4 = SENT;
            int M12 = max(Mm1, Mm2);
            int E0 = max(max(P0, M12), max(Mm3, E4m4));
            int E1 = max(max(P1, M12), Mm3);
            int E2 = max(max(P2, M12), S1m3);
            int E3 = max(max(P3, M12), S2m3);
            int E4 = max(max(P4, M12), S3m3);
            int En[NST] = {E0, E1, E2, E3, E4};
#pragma unroll
            for (int j = 0; j < NST; ++j) {
                int d = Et[j] - En[j];
                u[j] = (d < -126 || Et[j] <= SENT) ? 0.0f
                     : __int_as_float(mb[j] | ((d + 127) << 23));
            }
            int E4m1 = __shfl_up_sync(0xffffffffu, E4, 1); if (lane < 1) E4m1 = SENT;
            int E3m1 = __shfl_up_sync(0xffffffffu, E3, 1); if (lane < 1) E3m1 = SENT;
            int Em1[NST] = {E4m1, E0, E1, E2, E3};
            int Em2[NST] = {E3m1, E4m1, E0, E1, E2};
            float sb[NST], sc[NST];
#pragma unroll
            for (int j = 0; j < NST; ++j) {
                int db = min(Em1[j] - En[j], 126);
                sb[j] = (db < -126 || Em1[j] <= SENT) ? 0.0f : mkscale(db);
                int dc = min(Em2[j] - En[j], 126);
                float scv = (dc < -126 || Em2[j] <= SENT) ? 0.0f : mkscale(dc);
                sc[j] = skm[j] ? scv : 0.0f;
                Eb[j] = En[j];
            }
#pragma unroll
            for (int k = 0; k < RSTEPS; ++k) {
                int t = t0 + k;
                if (t <= tm) {
                    float vm1 = __shfl_up_sync(0xffffffffu, u[4], 1);
                    float vm2 = __shfl_up_sync(0xffffffffu, u[3], 1);
                    if (lane == 0) { vm1 = 0.0f; vm2 = 0.0f; }
                    float n0 = fmaf(vm2,  sc[0], fmaf(vm1,  sb[0], u[0])) * P[k][0];
                    float n1 = fmaf(vm1,  sc[1], fmaf(u[0], sb[1], u[1])) * P[k][1];
                    float n2 = fmaf(u[0], sc[2], fmaf(u[1], sb[2], u[2])) * P[k][2];
                    float n3 = fmaf(u[1], sc[3], fmaf(u[2], sb[3], u[3])) * P[k][3];
                    float n4 = fmaf(u[2], sc[4], fmaf(u[3], sb[4], u[4])) * P[k][4];
                    u[0] = n0; u[1] = n1; u[2] = n2; u[3] = n3; u[4] = n4;
                }
            }
            if (lane == 0) cons = tend;
        }
#pragma unroll
        for (int j = 0; j < NST; ++j) {
            int bits = __float_as_int(u[j]);
            int ex   = (bits >> 23) & 0xff;
            oute[lane * NST + j] = (ex == 0) ? SENT : (Eb[j] + ex - 127);
            outv[lane * NST + j] = (ex == 0) ? 0.0f
                                 : __int_as_float((bits & 0x007fffff) | 0x3f800000);
        }
    } else if (w == 0) {
        // ================= backward compute (gamma) =================
        int sk2m[NST];
#pragma unroll
        for (int j = 0; j < NST; ++j) {
            int s = lane * NST + j;
            int sk = 0;
            if ((s & 1) && (s + 2 <= L - 1)) {
                int lab  = tgt[s >> 1];
                int labp = tgt[(s >> 1) + 1];
                if (labp != 0 && labp != lab) sk = 1;
            }
            sk2m[j] = sk;
        }
        float u[NST]; int Eb[NST];
#pragma unroll
        for (int j = 0; j < NST; ++j) { u[j] = 0.0f; Eb[j] = SENT; }

        if (use_gamma) {
            int tl = tgt_len[b];
            int hi = 2 * tl; if (hi > L - 1) hi = L - 1;
            {
                int mx;
                do {
                    mx = ld_acquire_cta(&prog[0]);
#pragma unroll
                    for (int q = 1; q < NLD; ++q)
                        mx = max(mx, ld_acquire_cta(&prog[q]));
                } while (mx > lenm1);
                const float* rp = &ring[lenm1 & (RD - 1)][0];
#pragma unroll
                for (int j = 0; j < NST; ++j) {
                    int s = lane * NST + j;
                    if (tl > 0 && (s == hi || s == hi - 1)) {
                        u[j]  = rp[j * 32 + lane];
                        Eb[j] = 0;
                    }
                }
                if (lane == 0) cons = lenm1;
            }
            int mx = lenm1;
            for (int t0 = lenm1 - 1; t0 >= tmp1; t0 -= RSTEPS) {
                int tlow = t0 - RSTEPS + 1; if (tlow < tmp1) tlow = tmp1;
                if (mx > tlow) {
                    do {
                        mx = ld_acquire_cta(&prog[0]);
#pragma unroll
                        for (int q = 1; q < NLD; ++q)
                            mx = max(mx, ld_acquire_cta(&prog[q]));
                    } while (mx > tlow);
                }
                float P[RSTEPS][NST];
#pragma unroll
                for (int k = 0; k < RSTEPS; ++k) {
                    int t = t0 - k; if (t < tmp1) t = tmp1;
                    const float* rp = &ring[t & (RD - 1)][0];
#pragma unroll
                    for (int j = 0; j < NST; ++j) P[k][j] = rp[j * 32 + lane];
                }
                // rebase: E'[s] = max(Et[s..s+16])
                int Et[NST], mb[NST];
#pragma unroll
                for (int j = 0; j < NST; ++j) {
                    int bits = __float_as_int(u[j]);
                    int ex   = (bits >> 23) & 0xff;
                    Et[j] = (ex == 0) ? SENT : (Eb[j] + ex - 127);
                    mb[j] = bits & 0x007fffff;
                }
                int Pm1 = max(Et[0], Et[1]);
                int Pm2 = max(Pm1, Et[2]);
                int Pm3 = max(Pm2, Et[3]);
                int M   = max(Pm3, Et[4]);
                int Sm4 = Et[4];
                int Sm3 = max(Et[3], Sm4);
                int Sm2 = max(Et[2], Sm3);
                int Sm1 = max(Et[1], Sm2);
                int Sm0 = max(Et[0], Sm1);
                int Mp1  = __shfl_down_sync(0xffffffffu, M, 1);     if (lane > 30) Mp1  = SENT;
                int Mp2  = __shfl_down_sync(0xffffffffu, M, 2);     if (lane > 29) Mp2  = SENT;
                int Mp3  = __shfl_down_sync(0xffffffffu, M, 3);     if (lane > 28) Mp3  = SENT;
                int P1p3 = __shfl_down_sync(0xffffffffu, Pm1, 3);   if (lane > 28) P1p3 = SENT;
                int P2p3 = __shfl_down_sync(0xffffffffu, Pm2, 3);   if (lane > 28) P2p3 = SENT;
                int P3p3 = __shfl_down_sync(0xffffffffu, Pm3, 3);   if (lane > 28) P3p3 = SENT;
                int E0p4 = __shfl_down_sync(0xffffffffu, Et[0], 4); if (lane > 27) E0p4 = SENT;
                int M12 = max(Mp1, Mp2);
                int E0 = max(max(Sm0, M12), P1p3);
                int E1 = max(max(Sm1, M12), P2p3);
                int E2 = max(max(Sm2, M12), P3p3);
                int E3 = max(max(Sm3, M12), Mp3);
                int E4 = max(max(Sm4, M12), max(Mp3, E0p4));
                int En[NST] = {E0, E1, E2, E3, E4};
#pragma unroll
                for (int j = 0; j < NST; ++j) {
                    int d = Et[j] - En[j];
                    u[j] = (d < -126 || Et[j] <= SENT) ? 0.0f
                         : __int_as_float(mb[j] | ((d + 127) << 23));
                }
                int E0p1 = __shfl_down_sync(0xffffffffu, E0, 1); if (lane > 30) E0p1 = SENT;
                int E1p1 = __shfl_down_sync(0xffffffffu, E1, 1); if (lane > 30) E1p1 = SENT;
                int Ep1[NST] = {E1, E2, E3, E4, E0p1};
                int Ep2[NST] = {E2, E3, E4, E0p1, E1p1};
                float sb[NST], sc[NST];
#pragma unroll
                for (int j = 0; j < NST; ++j) {
                    int db = min(Ep1[j] - En[j], 126);
                    sb[j] = (db < -126 || Ep1[j] <= SENT) ? 0.0f : mkscale(db);
                    int dc = min(Ep2[j] - En[j], 126);
                    float scv = (dc < -126 || Ep2[j] <= SENT) ? 0.0f : mkscale(dc);
                    sc[j] = sk2m[j] ? scv : 0.0f;
                    Eb[j] = En[j];
                }
#pragma unroll
                for (int k = 0; k < RSTEPS; ++k) {
                    int t = t0 - k;
                    if (t >= tmp1) {
                        float d0 = __shfl_down_sync(0xffffffffu, u[0], 1);
                        float d1 = __shfl_down_sync(0xffffffffu, u[1], 1);
                        if (lane == 31) { d0 = 0.0f; d1 = 0.0f; }
                        float n0 = fmaf(u[2], sc[0], fmaf(u[1], sb[0], u[0])) * P[k][0];
                        float n1 = fmaf(u[3], sc[1], fmaf(u[2], sb[1], u[1])) * P[k][1];
                        float n2 = fmaf(u[4], sc[2], fmaf(u[3], sb[2], u[2])) * P[k][2];
                        float n3 = fmaf(d0,   sc[3], fmaf(u[4], sb[3], u[3])) * P[k][3];
                        float n4 = fmaf(d1,   sc[4], fmaf(d0,   sb[4], u[4])) * P[k][4];
                        u[0] = n0; u[1] = n1; u[2] = n2; u[3] = n3; u[4] = n4;
                    }
                }
                if (lane == 0) cons = tlow;
            }
        }
#pragma unroll
        for (int j = 0; j < NST; ++j) {
            int bits = __float_as_int(u[j]);
            int ex   = (bits >> 23) & 0xff;
            oute[lane * NST + j] = (ex == 0) ? SENT : (Eb[j] + ex - 127);
            outv[lane * NST + j] = (ex == 0) ? 0.0f
                                 : __int_as_float((bits & 0x007fffff) | 0x3f800000);
        }
    } else {
        // ================= loader warps (1..7) =================
        int lab2[NST];
#pragma unroll
        for (int j = 0; j < NST; ++j) {
            int s = lane * NST + j;
            int lab = 0;
            if (s < L && (s & 1)) lab = tgt[s >> 1];
            lab2[j] = lab;
        }
        const float* src = base + lane * 8;
        int i = w - 1;                               // 0..6
        if (dir == 0) {
            int cnt = (tm >= 1 + i) ? ((tm - 1 - i) / NLD + 1) : 0;
            loader_warp(src, BC, 1 + i, cnt, NLD, 1, max(tm, 1),
                        ring, &prog[i], &cons, +1, &scratchA[i][0], lab2, lane);
        } else {
            int start = lenm1 - i;
            int cnt = (start >= tmp1) ? ((start - tmp1) / NLD + 1) : 0;
            int lo = min(tmp1, lenm1); if (lo < 0) lo = 0;
            loader_warp(src, BC, start, cnt, -NLD, lo, lenm1,
                        ring, &prog[i], &cons, -1, &scratchA[i][0], lab2, lane);
        }
    }
    __syncthreads();

    // ---- pair rendezvous: second CTA combines ----
    if (tid == 0) {
        __threadfence();
        int old = atomicAdd(&g_pair[b], 1);
        if (old == 1) s_flags = 1;
    }
    __syncthreads();

    if ((s_flags & 1) && w == 0) {
        __threadfence();
        const float* avF = &g_fv[0][b][0]; const int* aeF = &g_fe[0][b][0];
        const float* gvB = &g_fv[1][b][0]; const int* geB = &g_fe[1][b][0];
        int tl = tgt_len[b];
        int hi = 2 * tl; if (hi > L - 1) hi = L - 1;
        float Tv[NST]; int Te[NST];
#pragma unroll
        for (int j = 0; j < NST; ++j) { Tv[j] = 0.0f; Te[j] = SENT; }
        if (tl > 0) {
#pragma unroll
            for (int j = 0; j < NST; ++j) {
                int s = lane * NST + j;
                if (s < L) {
                    float va = avF[s]; int ea = aeF[s];
                    if (va != 0.0f) {
                        if (use_gamma) {
                            float g0v = gvB[s];     int g0e = geB[s];
                            float g1v = 0.0f;       int g1e = SENT;
                            float g2v = 0.0f;       int g2e = SENT;
                            if (s + 1 <= L - 1) { g1v = gvB[s + 1]; g1e = geB[s + 1]; }
                            int sk2 = 0;
                            if ((s & 1) && (s + 2 <= L - 1)) {
                                int lab  = tgt[s >> 1];
                                int labp = tgt[(s >> 1) + 1];
                                if (labp != 0 && labp != lab) sk2 = 1;
                            }
                            if (sk2) { g2v = gvB[s + 2]; g2e = geB[s + 2]; }
                            if (g0v == 0.0f) g0e = SENT;
                            if (g1v == 0.0f) g1e = SENT;
                            if (g2v == 0.0f) g2e = SENT;
                            int m = max(g0e, max(g1e, g2e));
                            if (m > SENT / 2) {
                                float bsum = 0.0f;
                                if (g0e > SENT / 2 && g0e - m >= -126) bsum += g0v * mkscale(g0e - m);
                                if (g1e > SENT / 2 && g1e - m >= -126) bsum += g1v * mkscale(g1e - m);
                                if (g2e > SENT / 2 && g2e - m >= -126) bsum += g2v * mkscale(g2e - m);
                                if (bsum > 0.0f) { Tv[j] = va * bsum; Te[j] = ea + m; }
                            }
                        } else {
                            if (s == hi || s == hi - 1) { Tv[j] = va; Te[j] = ea; }
                        }
                    }
                }
            }
        }
        int M = SENT;
#pragma unroll
        for (int j = 0; j < NST; ++j) if (Tv[j] > 0.0f) M = max(M, Te[j]);
#pragma unroll
        for (int o = 16; o > 0; o >>= 1)
            M = max(M, __shfl_xor_sync(0xffffffffu, M, o));
        double acc = 0.0;
#pragma unroll
        for (int j = 0; j < NST; ++j) {
            if (Tv[j] > 0.0f) {
                long long d = (long long)Te[j] - M;
                if (d > -1000) {
                    unsigned long long bits2 = (unsigned long long)(d + 1023) << 52;
                    acc += (double)Tv[j] * __longlong_as_double((long long)bits2);
                }
            }
        }
#pragma unroll
        for (int o = 16; o > 0; o >>= 1)
            acc += __shfl_xor_sync(0xffffffffu, acc, o);
        if (lane == 0) {
            float loss = 0.0f;
            if (tl > 0 && acc > 0.0 && M > SENT / 2) {
                double ll = ((double)M + log2(acc)) * 0.69314718055994530942;
                loss = (float)(-ll / (double)tl);
            }
            g_loss[b] = loss;
            g_pair[b] = 0;                         // reset for next replay
            __threadfence();
            unsigned old = atomicAdd(&g_cnt, 1);
            if (old == (unsigned)(B - 1)) s_flags |= 2;
        }
    }
    __syncthreads();

    // ---- last combining CTA: fused mean reduction ----
    if (s_flags & 2) {
        __threadfence();
        float acc2 = 0.0f;
        for (int i2 = tid; i2 < B; i2 += 256) acc2 += g_loss[i2];
#pragma unroll
        for (int o = 16; o > 0; o >>= 1)
            acc2 += __shfl_xor_sync(0xffffffffu, acc2, o);
        if (lane == 0) red[w] = acc2;
        __syncthreads();
        if (tid == 0) {
            float s8 = 0.0f;
#pragma unroll
            for (int k = 0; k < 8; ++k) s8 += red[k];
            out[0] = s8 / (float)B;
            g_cnt = 0;                             // reset for next replay
        }
    }
}

extern "C" void kernel_launch(void* const* d_in, const int* in_sizes, int n_in,
                              void* d_out, int out_size)
{
    const float* logp    = (const float*)d_in[0];
    const int*   targets = (const int*)d_in[1];
    const int*   in_len  = (const int*)d_in[2];
    const int*   tgt_len = (const int*)d_in[3];

    int B = in_sizes[2];                                   // 128
    int S = in_sizes[1] / B;                               // 64
    int C = 256;
    int T = (int)((size_t)in_sizes[0] / ((size_t)B * C));  // 1024

    ctc_split_kernel<<<2 * B, 256>>>(logp, targets, in_len, tgt_len,
                                     (float*)d_out, T, B, C, S);
}